// round 15
// baseline (speedup 1.0000x reference)
#include <cuda_runtime.h>
#include <cuda_bf16.h>
#include <cstdint>

#define BS   4
#define NQ   1024
#define D    256
#define NH   8
#define NP   4
#define LNUM 6
#define DFF  1024
#define H_BEV 200
#define W_BEV 150
#define NV   (H_BEV * W_BEV)
#define DH   32
#define MROWS (BS * NQ)          // 4096

// ------------------------- scratch (static device globals) -------------------------
__device__ float g_xbuf[MROWS * D];
__device__ float g_qk[MROWS * 512];
__device__ float g_v[MROWS * D];
__device__ float g_sa[MROWS * D];
__device__ float g_t1[MROWS * D];
__device__ float g_t2[MROWS * D];
__device__ float g_val[(size_t)LNUM * BS * NV * D];
__device__ float g_ow[LNUM * 128 * D];     // packed off+aw weights
__device__ float g_ob[LNUM * 128];         // packed off+aw bias
__device__ float g_offaw[MROWS * 128];
__device__ float g_ca[MROWS * D];
__device__ float g_ffn[MROWS * DFF];

// ------------------------- stream/event aux -------------------------
struct Aux {
    cudaStream_t sB = 0, sC = 0;
    cudaEvent_t fork = 0;
    cudaEvent_t val_ev[LNUM] = {};
    cudaEvent_t ev_x[LNUM] = {};
    cudaEvent_t ev_v[LNUM] = {};
    bool ok = false;
    Aux() {
        if (cudaStreamCreateWithFlags(&sB, cudaStreamNonBlocking) != cudaSuccess) return;
        if (cudaStreamCreateWithFlags(&sC, cudaStreamNonBlocking) != cudaSuccess) return;
        if (cudaEventCreateWithFlags(&fork, cudaEventDisableTiming) != cudaSuccess) return;
        for (int i = 0; i < LNUM; i++) {
            if (cudaEventCreateWithFlags(&val_ev[i], cudaEventDisableTiming) != cudaSuccess) return;
            if (cudaEventCreateWithFlags(&ev_x[i], cudaEventDisableTiming) != cudaSuccess) return;
            if (cudaEventCreateWithFlags(&ev_v[i], cudaEventDisableTiming) != cudaSuccess) return;
        }
        ok = true;
    }
};
static Aux g_aux;

// ------------------------- helpers -------------------------
__device__ __forceinline__ uint32_t f2tf(float f) {
    uint32_t r;
    asm("cvt.rna.tf32.f32 %0, %1;" : "=r"(r) : "f"(f));
    return r;
}
__device__ __forceinline__ void mma_tf32(float* c, const uint32_t* a, const uint32_t* b) {
    asm volatile("mma.sync.aligned.m16n8k8.row.col.f32.tf32.tf32.f32 "
                 "{%0,%1,%2,%3},{%4,%5,%6,%7},{%8,%9},{%0,%1,%2,%3};"
                 : "+f"(c[0]), "+f"(c[1]), "+f"(c[2]), "+f"(c[3])
                 : "r"(a[0]), "r"(a[1]), "r"(a[2]), "r"(a[3]), "r"(b[0]), "r"(b[1]));
}
__device__ __forceinline__ void cp16(uint32_t smem_addr, const void* gptr, int src_bytes) {
    asm volatile("cp.async.ca.shared.global [%0], [%1], 16, %2;\n"
                 :: "r"(smem_addr), "l"(gptr), "r"(src_bytes));
}
__device__ __forceinline__ void cp16cg(uint32_t smem_addr, const void* gptr, int src_bytes) {
    asm volatile("cp.async.cg.shared.global [%0], [%1], 16, %2;\n"
                 :: "r"(smem_addr), "l"(gptr), "r"(src_bytes));
}
__device__ __forceinline__ void cp_commit() { asm volatile("cp.async.commit_group;\n"); }
template <int N>
__device__ __forceinline__ void cp_wait() { asm volatile("cp.async.wait_group %0;\n" :: "n"(N)); }

// ------------------------- elementwise add -------------------------
__global__ void add_kernel(const float* __restrict__ a, const float* __restrict__ b,
                           float* __restrict__ o, int n) {
    int i = blockIdx.x * blockDim.x + threadIdx.x;
    if (i < n) o[i] = a[i] + b[i];
}

// ------------------------- pack off+aw weights -------------------------
__global__ void pack_offaw(const float* __restrict__ offw, const float* __restrict__ offb,
                           const float* __restrict__ aww, const float* __restrict__ awb,
                           float* __restrict__ W, float* __restrict__ B) {
    int i = blockIdx.x * blockDim.x + threadIdx.x;
    const int total = LNUM * 128 * D;
    if (i < total) {
        int l = i / (128 * D);
        int r = (i / D) % 128;
        int c = i % D;
        float v = 0.f;
        if (r < 64)      v = offw[((size_t)l * 64 + r) * D + c];
        else if (r < 96) v = aww[((size_t)l * 32 + (r - 64)) * D + c];
        W[i] = v;
    }
    if (i < LNUM * 128) {
        int l = i / 128, r = i % 128;
        float v = 0.f;
        if (r < 64)      v = offb[l * 64 + r];
        else if (r < 96) v = awb[l * 32 + (r - 64)];
        B[i] = v;
    }
}

// ------------------------- tf32 tensor-core GEMM (BK=32, padded smem) -------------------------
// C[M,N] = A[M,K] @ W[N,K]^T + bias. K must be a multiple of 32.
template <int BM, int BN, bool RELU>
__global__ __launch_bounds__(256)
void gemm_tc(const float* __restrict__ A, const float* __restrict__ W,
             const float* __restrict__ bias, float* __restrict__ C,
             int M, int N, int K) {
    constexpr int ST  = 3;
    constexpr int LDB = 36;              // 32 k-words + 4 pad (row = 144B, 16B-aligned)
    constexpr int WMC = (BM >= 32) ? (BM / 32) : 1;
    constexpr int WNC = 8 / WMC;
    constexpr int WCOLS = BN / WNC;
    constexpr int NT  = WCOLS / 8;

    __shared__ uint32_t As[ST][BM * LDB];
    __shared__ uint32_t Bs[ST][BN * LDB];

    const int tid  = threadIdx.x;
    const int lane = tid & 31;
    const int wid  = tid >> 5;
    const int wm   = wid % WMC;
    const int wn   = wid / WMC;
    const int g    = lane >> 2;
    const int t    = lane & 3;
    const int m0   = blockIdx.y * BM;
    const int n0   = blockIdx.x * BN;

    auto load_stage = [&](int s, int kt) {
        const int k0 = kt * 32;
        uint32_t sa = (uint32_t)__cvta_generic_to_shared(&As[s][0]);
        uint32_t sb = (uint32_t)__cvta_generic_to_shared(&Bs[s][0]);
#pragma unroll
        for (int c = tid; c < (BM + BN) * 8; c += 256) {
            int row = c >> 3, cg = (c & 7) * 4;
            if (c < BM * 8) {
                int gm = m0 + row;
                cp16cg(sa + (row * LDB + cg) * 4, &A[(size_t)gm * K + k0 + cg], gm < M ? 16 : 0);
            } else {
                int r = row - BM;
                cp16cg(sb + (r * LDB + cg) * 4, &W[(size_t)(n0 + r) * K + k0 + cg], 16);
            }
        }
        cp_commit();
    };

    float acc[2][NT][4];
#pragma unroll
    for (int i = 0; i < 2; i++)
#pragma unroll
        for (int j = 0; j < NT; j++)
#pragma unroll
            for (int c = 0; c < 4; c++) acc[i][j][c] = 0.f;

    const int KT = K / 32;
    load_stage(0, 0);
    if (KT > 1) load_stage(1 % ST, 1);

    for (int kt = 0; kt < KT; kt++) {
        cp_wait<1>();
        __syncthreads();
        if (kt + 2 < KT) load_stage((kt + 2) % ST, kt + 2);
        const int s = kt % ST;

#pragma unroll
        for (int kh = 0; kh < 2; kh++) {
            uint32_t afA[2][4], afB[2][4];
#pragma unroll
            for (int mt = 0; mt < 2; mt++) {
                const int row = wm * 32 + mt * 16 + g;
                uint4 ar0 = *reinterpret_cast<const uint4*>(&As[s][row * LDB + kh * 16 + t * 4]);
                uint4 ar1 = *reinterpret_cast<const uint4*>(&As[s][(row + 8) * LDB + kh * 16 + t * 4]);
                afA[mt][0] = ar0.x; afA[mt][1] = ar1.x; afA[mt][2] = ar0.y; afA[mt][3] = ar1.y;
                afB[mt][0] = ar0.z; afB[mt][1] = ar1.z; afB[mt][2] = ar0.w; afB[mt][3] = ar1.w;
            }
#pragma unroll
            for (int nt = 0; nt < NT; nt++) {
                uint4 br = *reinterpret_cast<const uint4*>(
                    &Bs[s][(wn * WCOLS + nt * 8 + g) * LDB + kh * 16 + t * 4]);
                uint32_t bA[2] = {br.x, br.y};
                uint32_t bB[2] = {br.z, br.w};
#pragma unroll
                for (int mt = 0; mt < 2; mt++) {
                    mma_tf32(acc[mt][nt], afA[mt], bA);
                    mma_tf32(acc[mt][nt], afB[mt], bB);
                }
            }
        }
    }

#pragma unroll
    for (int nt = 0; nt < NT; nt++) {
        const int cb = n0 + wn * WCOLS + nt * 8 + t * 2;
        const float bv0 = bias[cb], bv1 = bias[cb + 1];
#pragma unroll
        for (int mt = 0; mt < 2; mt++) {
            int r0 = m0 + wm * 32 + mt * 16 + g;
            float o0 = acc[mt][nt][0] + bv0, o1 = acc[mt][nt][1] + bv1;
            float o2 = acc[mt][nt][2] + bv0, o3 = acc[mt][nt][3] + bv1;
            if (RELU) {
                o0 = fmaxf(o0, 0.f); o1 = fmaxf(o1, 0.f);
                o2 = fmaxf(o2, 0.f); o3 = fmaxf(o3, 0.f);
            }
            if (r0 < M)
                *reinterpret_cast<float2*>(&C[(size_t)r0 * N + cb]) = make_float2(o0, o1);
            if (r0 + 8 < M)
                *reinterpret_cast<float2*>(&C[(size_t)(r0 + 8) * N + cb]) = make_float2(o2, o3);
        }
    }
}

// ------------------------- fused GEMM + bias + residual + LayerNorm (R8 mainloop) ---------
__global__ __launch_bounds__(256)
void gemm_ln(const float* __restrict__ A, const float* __restrict__ W,
             const float* __restrict__ bias, const float* __restrict__ resid,
             const float* __restrict__ lnw, const float* __restrict__ lnb,
             float* __restrict__ C, const float* __restrict__ qpos,
             float* __restrict__ C2, int M, int K) {
    constexpr int ST = 3, BM = 32, BN = 256, NT = 4, WCOLS = 32;
    __shared__ uint32_t As[ST][BM * 16];
    __shared__ uint32_t Bs[ST][BN * 16];
    __shared__ float s_sum[BM][8];
    __shared__ float s_sq[BM][8];

    const int tid  = threadIdx.x;
    const int lane = tid & 31;
    const int wn   = tid >> 5;
    const int g    = lane >> 2;
    const int t    = lane & 3;
    const int m0   = blockIdx.y * BM;

    auto load_stage = [&](int s, int kt) {
        const int k0 = kt * 16;
        uint32_t sa = (uint32_t)__cvta_generic_to_shared(&As[s][0]);
        uint32_t sb = (uint32_t)__cvta_generic_to_shared(&Bs[s][0]);
#pragma unroll
        for (int c = tid; c < (BM + BN) * 4; c += 256) {
            int row = c >> 2, cg = (c & 3) * 4;
            if (c < BM * 4) {
                cp16(sa + (row * 16 + cg) * 4, &A[(size_t)(m0 + row) * K + k0 + cg], 16);
            } else {
                int r = row - BM;
                cp16(sb + (r * 16 + cg) * 4, &W[(size_t)r * K + k0 + cg], 16);
            }
        }
        cp_commit();
    };

    float acc[2][NT][4];
#pragma unroll
    for (int i = 0; i < 2; i++)
#pragma unroll
        for (int j = 0; j < NT; j++)
#pragma unroll
            for (int c = 0; c < 4; c++) acc[i][j][c] = 0.f;

    const int KT = K / 16;
    load_stage(0, 0);
    if (KT > 1) load_stage(1 % ST, 1);

    for (int kt = 0; kt < KT; kt++) {
        cp_wait<1>();
        __syncthreads();
        if (kt + 2 < KT) load_stage((kt + 2) % ST, kt + 2);
        const int s = kt % ST;

        uint32_t afA[2][4], afB[2][4];
#pragma unroll
        for (int mt = 0; mt < 2; mt++) {
            const int row = mt * 16 + g;
            uint4 ar0 = *reinterpret_cast<const uint4*>(&As[s][row * 16 + t * 4]);
            uint4 ar1 = *reinterpret_cast<const uint4*>(&As[s][(row + 8) * 16 + t * 4]);
            afA[mt][0] = ar0.x; afA[mt][1] = ar1.x; afA[mt][2] = ar0.y; afA[mt][3] = ar1.y;
            afB[mt][0] = ar0.z; afB[mt][1] = ar1.z; afB[mt][2] = ar0.w; afB[mt][3] = ar1.w;
        }
#pragma unroll
        for (int nt = 0; nt < NT; nt++) {
            uint4 br = *reinterpret_cast<const uint4*>(&Bs[s][(wn * WCOLS + nt * 8 + g) * 16 + t * 4]);
            uint32_t bA[2] = {br.x, br.y};
            uint32_t bB[2] = {br.z, br.w};
#pragma unroll
            for (int mt = 0; mt < 2; mt++) {
                mma_tf32(acc[mt][nt], afA[mt], bA);
                mma_tf32(acc[mt][nt], afB[mt], bB);
            }
        }
    }

    float vals[2][NT][4];
    float rsum[4] = {0.f, 0.f, 0.f, 0.f};
    float rsq[4]  = {0.f, 0.f, 0.f, 0.f};
#pragma unroll
    for (int mt = 0; mt < 2; mt++) {
        const int r0 = m0 + mt * 16 + g, r1 = r0 + 8;
#pragma unroll
        for (int nt = 0; nt < NT; nt++) {
            const int cb = wn * WCOLS + nt * 8 + t * 2;
            const float b0 = bias[cb], b1 = bias[cb + 1];
            float2 rr0 = *reinterpret_cast<const float2*>(&resid[(size_t)r0 * 256 + cb]);
            float2 rr1 = *reinterpret_cast<const float2*>(&resid[(size_t)r1 * 256 + cb]);
            float v0 = acc[mt][nt][0] + b0 + rr0.x;
            float v1 = acc[mt][nt][1] + b1 + rr0.y;
            float v2 = acc[mt][nt][2] + b0 + rr1.x;
            float v3 = acc[mt][nt][3] + b1 + rr1.y;
            vals[mt][nt][0] = v0; vals[mt][nt][1] = v1;
            vals[mt][nt][2] = v2; vals[mt][nt][3] = v3;
            rsum[mt * 2]     += v0 + v1;  rsq[mt * 2]     += v0 * v0 + v1 * v1;
            rsum[mt * 2 + 1] += v2 + v3;  rsq[mt * 2 + 1] += v2 * v2 + v3 * v3;
        }
    }
    const unsigned F = 0xffffffffu;
#pragma unroll
    for (int sl = 0; sl < 4; sl++) {
        rsum[sl] += __shfl_xor_sync(F, rsum[sl], 1);
        rsum[sl] += __shfl_xor_sync(F, rsum[sl], 2);
        rsq[sl]  += __shfl_xor_sync(F, rsq[sl], 1);
        rsq[sl]  += __shfl_xor_sync(F, rsq[sl], 2);
    }
    if (t == 0) {
#pragma unroll
        for (int sl = 0; sl < 4; sl++) {
            int rowl = (sl >> 1) * 16 + g + (sl & 1) * 8;
            s_sum[rowl][wn] = rsum[sl];
            s_sq[rowl][wn]  = rsq[sl];
        }
    }
    __syncthreads();

    float mean_[4], rstd_[4];
#pragma unroll
    for (int sl = 0; sl < 4; sl++) {
        int rowl = (sl >> 1) * 16 + g + (sl & 1) * 8;
        float sv = 0.f, q = 0.f;
#pragma unroll
        for (int w8 = 0; w8 < 8; w8++) { sv += s_sum[rowl][w8]; q += s_sq[rowl][w8]; }
        float mean = sv * (1.f / 256.f);
        float var  = q * (1.f / 256.f) - mean * mean;
        mean_[sl] = mean;
        rstd_[sl] = rsqrtf(var + 1e-5f);
    }

#pragma unroll
    for (int mt = 0; mt < 2; mt++) {
        const int r0 = m0 + mt * 16 + g, r1 = r0 + 8;
        const float mA = mean_[mt * 2],     rA = rstd_[mt * 2];
        const float mB = mean_[mt * 2 + 1], rB = rstd_[mt * 2 + 1];
#pragma unroll
        for (int nt = 0; nt < NT; nt++) {
            const int cb = wn * WCOLS + nt * 8 + t * 2;
            const float w0 = lnw[cb], w1 = lnw[cb + 1];
            const float lb0 = lnb[cb], lb1 = lnb[cb + 1];
            float o0 = (vals[mt][nt][0] - mA) * rA * w0 + lb0;
            float o1 = (vals[mt][nt][1] - mA) * rA * w1 + lb1;
            float o2 = (vals[mt][nt][2] - mB) * rB * w0 + lb0;
            float o3 = (vals[mt][nt][3] - mB) * rB * w1 + lb1;
            *reinterpret_cast<float2*>(&C[(size_t)r0 * 256 + cb]) = make_float2(o0, o1);
            *reinterpret_cast<float2*>(&C[(size_t)r1 * 256 + cb]) = make_float2(o2, o3);
            if (C2) {
                float2 q0 = *reinterpret_cast<const float2*>(&qpos[(size_t)r0 * 256 + cb]);
                float2 q1 = *reinterpret_cast<const float2*>(&qpos[(size_t)r1 * 256 + cb]);
                *reinterpret_cast<float2*>(&C2[(size_t)r0 * 256 + cb]) =
                    make_float2(o0 + q0.x, o1 + q0.y);
                *reinterpret_cast<float2*>(&C2[(size_t)r1 * 256 + cb]) =
                    make_float2(o2 + q1.x, o3 + q1.y);
            }
        }
    }
}

// ------------------------- tensor-core flash attention (cp.async double-buffered) ----------
#define LKP 36
#define LVP 40
__global__ __launch_bounds__(256)
void attn_tc_kernel(const float* __restrict__ QK, const float* __restrict__ V,
                    float* __restrict__ O) {
    __shared__ uint32_t Ks[2][64 * LKP];
    __shared__ uint32_t Vs[2][64 * LVP];

    const int q0   = blockIdx.x * 128;
    const int h    = blockIdx.y;
    const int b    = blockIdx.z;
    const int tid  = threadIdx.x;
    const int lane = tid & 31;
    const int w    = tid >> 5;
    const int g    = lane >> 2;
    const int t    = lane & 3;

    auto load_tile = [&](int bufi, int t0) {
        uint32_t kb = (uint32_t)__cvta_generic_to_shared(&Ks[bufi][0]);
        uint32_t vbs = (uint32_t)__cvta_generic_to_shared(&Vs[bufi][0]);
#pragma unroll
        for (int j = 0; j < 2; j++) {
            int c = tid + j * 256;
            int row = c >> 3, cg = (c & 7) * 4;
            cp16(kb + (row * LKP + cg) * 4,
                 &QK[(size_t)(b * NQ + t0 + row) * 512 + 256 + h * 32 + cg], 16);
        }
#pragma unroll
        for (int j = 0; j < 2; j++) {
            int c = tid + j * 256;
            int row = c >> 3, cg = (c & 7) * 4;
            cp16(vbs + (row * LVP + cg) * 4,
                 &V[(size_t)(b * NQ + t0 + row) * 256 + h * 32 + cg], 16);
        }
        cp_commit();
    };

    uint32_t af[4][4];
    {
        const int r0 = b * NQ + q0 + w * 16 + g;
        const int r1 = r0 + 8;
        const float scq = 0.17677669529663687f;
        const float* Q0 = &QK[(size_t)r0 * 512 + h * 32];
        const float* Q1 = &QK[(size_t)r1 * 512 + h * 32];
#pragma unroll
        for (int ks = 0; ks < 4; ks++) {
            af[ks][0] = f2tf(Q0[ks * 8 + t] * scq);
            af[ks][1] = f2tf(Q1[ks * 8 + t] * scq);
            af[ks][2] = f2tf(Q0[ks * 8 + t + 4] * scq);
            af[ks][3] = f2tf(Q1[ks * 8 + t + 4] * scq);
        }
    }

    float oc[4][4];
#pragma unroll
    for (int i = 0; i < 4; i++)
#pragma unroll
        for (int j = 0; j < 4; j++) oc[i][j] = 0.f;
    float m0r = -1e30f, m1r = -1e30f, l0 = 0.f, l1 = 0.f;
    const unsigned F = 0xffffffffu;

    load_tile(0, 0);
    int buf = 0;
    const int NTILES = NQ / 64;

    for (int it = 0; it < NTILES; it++) {
        if (it + 1 < NTILES) {
            load_tile(buf ^ 1, (it + 1) * 64);
            cp_wait<1>();
        } else {
            cp_wait<0>();
        }
        __syncthreads();

        float sc[8][4];
#pragma unroll
        for (int nt = 0; nt < 8; nt++) {
            sc[nt][0] = sc[nt][1] = sc[nt][2] = sc[nt][3] = 0.f;
            uint32_t bf[4][2];
#pragma unroll
            for (int ks = 0; ks < 4; ks++) {
                const uint32_t* base = &Ks[buf][(nt * 8 + g) * LKP + ks * 8];
                bf[ks][0] = base[t];
                bf[ks][1] = base[t + 4];
            }
#pragma unroll
            for (int ks = 0; ks < 4; ks++) mma_tf32(sc[nt], af[ks], bf[ks]);
        }

        float mt0 = -1e30f, mt1 = -1e30f;
#pragma unroll
        for (int nt = 0; nt < 8; nt++) {
            mt0 = fmaxf(mt0, fmaxf(sc[nt][0], sc[nt][1]));
            mt1 = fmaxf(mt1, fmaxf(sc[nt][2], sc[nt][3]));
        }
        mt0 = fmaxf(mt0, __shfl_xor_sync(F, mt0, 1));
        mt0 = fmaxf(mt0, __shfl_xor_sync(F, mt0, 2));
        mt1 = fmaxf(mt1, __shfl_xor_sync(F, mt1, 1));
        mt1 = fmaxf(mt1, __shfl_xor_sync(F, mt1, 2));
        const float mn0 = fmaxf(m0r, mt0), mn1 = fmaxf(m1r, mt1);
        const float sc0 = __expf(m0r - mn0), sc1 = __expf(m1r - mn1);

        uint32_t pf[8][4];
        float s0 = 0.f, s1 = 0.f;
#pragma unroll
        for (int nt = 0; nt < 8; nt++) {
            float p0 = __expf(sc[nt][0] - mn0);
            float p1 = __expf(sc[nt][1] - mn0);
            float p2 = __expf(sc[nt][2] - mn1);
            float p3 = __expf(sc[nt][3] - mn1);
            s0 += p0 + p1; s1 += p2 + p3;
            pf[nt][0] = f2tf(p0); pf[nt][1] = f2tf(p1);
            pf[nt][2] = f2tf(p2); pf[nt][3] = f2tf(p3);
        }
        s0 += __shfl_xor_sync(F, s0, 1); s0 += __shfl_xor_sync(F, s0, 2);
        s1 += __shfl_xor_sync(F, s1, 1); s1 += __shfl_xor_sync(F, s1, 2);
        l0 = l0 * sc0 + s0;
        l1 = l1 * sc1 + s1;
        m0r = mn0; m1r = mn1;
#pragma unroll
        for (int nt = 0; nt < 4; nt++) {
            oc[nt][0] *= sc0; oc[nt][1] *= sc0;
            oc[nt][2] *= sc1; oc[nt][3] *= sc1;
        }

        const int src0 = (lane & ~3) | (t >> 1);
        const int src1 = src0 + 2;
        const bool odd = (t & 1);
#pragma unroll
        for (int kt = 0; kt < 8; kt++) {
            uint32_t a[4];
            uint32_t x0 = __shfl_sync(F, pf[kt][0], src0);
            uint32_t x1 = __shfl_sync(F, pf[kt][1], src0);
            a[0] = odd ? x1 : x0;
            uint32_t x2 = __shfl_sync(F, pf[kt][2], src0);
            uint32_t x3 = __shfl_sync(F, pf[kt][3], src0);
            a[1] = odd ? x3 : x2;
            x0 = __shfl_sync(F, pf[kt][0], src1);
            x1 = __shfl_sync(F, pf[kt][1], src1);
            a[2] = odd ? x1 : x0;
            x2 = __shfl_sync(F, pf[kt][2], src1);
            x3 = __shfl_sync(F, pf[kt][3], src1);
            a[3] = odd ? x3 : x2;
#pragma unroll
            for (int nt = 0; nt < 4; nt++) {
                uint32_t bfv[2];
                bfv[0] = Vs[buf][(kt * 8 + t) * LVP + nt * 8 + g];
                bfv[1] = Vs[buf][(kt * 8 + t + 4) * LVP + nt * 8 + g];
                mma_tf32(oc[nt], a, bfv);
            }
        }
        __syncthreads();
        buf ^= 1;
    }

    const float inv0 = 1.f / l0, inv1 = 1.f / l1;
    const int r0 = b * NQ + q0 + w * 16 + g;
#pragma unroll
    for (int nt = 0; nt < 4; nt++) {
        const int col = h * 32 + nt * 8 + t * 2;
        *reinterpret_cast<float2*>(&O[(size_t)r0 * 256 + col]) =
            make_float2(oc[nt][0] * inv0, oc[nt][1] * inv0);
        *reinterpret_cast<float2*>(&O[(size_t)(r0 + 8) * 256 + col]) =
            make_float2(oc[nt][2] * inv1, oc[nt][3] * inv1);
    }
}

// ------------------------- MSDA sampling -------------------------
__global__ void msda_kernel(const float* __restrict__ val, const float* __restrict__ offaw,
                            const float* __restrict__ ref, const int* __restrict__ lsi,
                            float* __restrict__ out) {
    const int warp = (blockIdx.x * blockDim.x + threadIdx.x) >> 5;
    const int lane = threadIdx.x & 31;
    if (warp >= BS * NQ * NH) return;
    const int h  = warp % NH;
    const int bq = warp / NH;
    const int b  = bq / NQ;
    const int base = lsi[0];

    const float rx = ref[bq * 2 + 0] * (float)W_BEV - 0.5f;
    const float ry = ref[bq * 2 + 1] * (float)H_BEV - 0.5f;

    const float* row = &offaw[(size_t)bq * 128];
    float a0 = row[64 + h * NP + 0];
    float a1 = row[64 + h * NP + 1];
    float a2 = row[64 + h * NP + 2];
    float a3 = row[64 + h * NP + 3];
    float mx = fmaxf(fmaxf(a0, a1), fmaxf(a2, a3));
    float e0 = __expf(a0 - mx), e1 = __expf(a1 - mx), e2 = __expf(a2 - mx), e3 = __expf(a3 - mx);
    float inv = 1.f / (e0 + e1 + e2 + e3);
    float ap[4] = {e0 * inv, e1 * inv, e2 * inv, e3 * inv};

    float accv = 0.f;
#pragma unroll
    for (int p = 0; p < NP; p++) {
        float ox = row[(h * NP + p) * 2 + 0];
        float oy = row[(h * NP + p) * 2 + 1];
        float x = rx + ox, y = ry + oy;
        float x0f = floorf(x), y0f = floorf(y);
        int x0 = (int)x0f, y0 = (int)y0f;
        float fx = x - x0f, fy = y - y0f;
        float wgt[4] = {(1.f - fx) * (1.f - fy), fx * (1.f - fy), (1.f - fx) * fy, fx * fy};
        int xs[4] = {x0, x0 + 1, x0, x0 + 1};
        int ys[4] = {y0, y0, y0 + 1, y0 + 1};
#pragma unroll
        for (int c = 0; c < 4; c++) {
            int xi = xs[c], yi = ys[c];
            if (xi >= 0 && xi < W_BEV && yi >= 0 && yi < H_BEV) {
                float vv = val[((size_t)(b * NV + base + yi * W_BEV + xi)) * D + h * DH + lane];
                accv += ap[p] * wgt[c] * vv;
            }
        }
    }
    out[(size_t)bq * D + h * DH + lane] = accv;
}

// ------------------------- refs tail -------------------------
__global__ void copy_refs_kernel(const float* __restrict__ ref, float* __restrict__ out) {
    int i = blockIdx.x * blockDim.x + threadIdx.x;
    const int n1 = BS * NQ * 2;
    if (i < LNUM * n1) out[i] = ref[i % n1];
}

// ------------------------- launch -------------------------
extern "C" void kernel_launch(void* const* d_in, const int* in_sizes, int n_in,
                              void* d_out, int out_size) {
    const float* query    = (const float*)d_in[0];
    const float* qpos     = (const float*)d_in[1];
    const float* ref      = (const float*)d_in[2];
    const float* src      = (const float*)d_in[3];
    const int*   lsi      = (const int*)d_in[5];
    const float* sa_in_w  = (const float*)d_in[6];
    const float* sa_in_b  = (const float*)d_in[7];
    const float* sa_out_w = (const float*)d_in[8];
    const float* sa_out_b = (const float*)d_in[9];
    const float* ca_off_w = (const float*)d_in[10];
    const float* ca_off_b = (const float*)d_in[11];
    const float* ca_aw_w  = (const float*)d_in[12];
    const float* ca_aw_b  = (const float*)d_in[13];
    const float* ca_val_w = (const float*)d_in[14];
    const float* ca_val_b = (const float*)d_in[15];
    const float* ca_out_w = (const float*)d_in[16];
    const float* ca_out_b = (const float*)d_in[17];
    const float* n1_w     = (const float*)d_in[18];
    const float* n1_b     = (const float*)d_in[19];
    const float* n2_w     = (const float*)d_in[20];
    const float* n2_b     = (const float*)d_in[21];
    const float* n3_w     = (const float*)d_in[22];
    const float* n3_b     = (const float*)d_in[23];
    const float* ff1_w    = (const float*)d_in[24];
    const float* ff1_b    = (const float*)d_in[25];
    const float* ff2_w    = (const float*)d_in[26];
    const float* ff2_b    = (const float*)d_in[27];

    float *xbuf, *qkb, *vb, *sab, *t1b, *t2b, *valb, *owb, *obb, *offawb, *cab, *ffnb;
    cudaGetSymbolAddress((void**)&xbuf, g_xbuf);
    cudaGetSymbolAddress((void**)&qkb,  g_qk);
    cudaGetSymbolAddress((void**)&vb,   g_v);
    cudaGetSymbolAddress((void**)&sab,  g_sa);
    cudaGetSymbolAddress((void**)&t1b,  g_t1);
    cudaGetSymbolAddress((void**)&t2b,  g_t2);
    cudaGetSymbolAddress((void**)&valb, g_val);
    cudaGetSymbolAddress((void**)&owb,  g_ow);
    cudaGetSymbolAddress((void**)&obb,  g_ob);
    cudaGetSymbolAddress((void**)&offawb, g_offaw);
    cudaGetSymbolAddress((void**)&cab,  g_ca);
    cudaGetSymbolAddress((void**)&ffnb, g_ffn);

    float* out_hs = (float*)d_out;
    const int NTOK = MROWS * D;
    const size_t VAL_STRIDE = (size_t)BS * NV * D;

    const bool use_s = g_aux.ok;
    cudaStream_t sB = use_s ? g_aux.sB : 0;
    cudaStream_t sC = use_s ? g_aux.sC : 0;

    pack_offaw<<<(LNUM * 128 * D + 255) / 256, 256>>>(ca_off_w, ca_off_b, ca_aw_w, ca_aw_b,
                                                      owb, obb);

    if (use_s) {
        cudaEventRecord(g_aux.fork, 0);
        cudaStreamWaitEvent(sB, g_aux.fork, 0);
        cudaStreamWaitEvent(sC, g_aux.fork, 0);
    }
    for (int l = 0; l < LNUM; l++) {
        gemm_tc<128, 128, false><<<dim3(D / 128, (BS * NV + 127) / 128), 256, 0, sB>>>(
            src, ca_val_w + (size_t)l * D * D, ca_val_b + (size_t)l * D,
            valb + (size_t)l * VAL_STRIDE, BS * NV, D, D);
        if (use_s) cudaEventRecord(g_aux.val_ev[l], sB);
    }

    add_kernel<<<(NTOK + 255) / 256, 256>>>(query, qpos, xbuf, NTOK);
    if (use_s) cudaEventRecord(g_aux.ev_x[0], 0);

    for (int l = 0; l < LNUM; l++) {
        const float* prev = (l == 0) ? query : out_hs + (size_t)(l - 1) * NTOK;
        float* cur = out_hs + (size_t)l * NTOK;

        if (use_s) {
            cudaStreamWaitEvent(sC, g_aux.ev_x[l], 0);
            gemm_tc<64, 128, false><<<dim3(D / 128, MROWS / 64), 256, 0, sC>>>(
                prev, sa_in_w + (size_t)l * 3 * D * D + (size_t)2 * D * D,
                sa_in_b + (size_t)l * 3 * D + 2 * D, vb, MROWS, D, D);
            cudaEventRecord(g_aux.ev_v[l], sC);
        } else {
            gemm_tc<64, 128, false><<<dim3(D / 128, MROWS / 64), 256>>>(
                prev, sa_in_w + (size_t)l * 3 * D * D + (size_t)2 * D * D,
                sa_in_b + (size_t)l * 3 * D + 2 * D, vb, MROWS, D, D);
        }

        gemm_tc<64, 128, false><<<dim3(512 / 128, MROWS / 64), 256>>>(
            xbuf, sa_in_w + (size_t)l * 3 * D * D, sa_in_b + (size_t)l * 3 * D,
            qkb, MROWS, 512, D);
        if (use_s) cudaStreamWaitEvent(0, g_aux.ev_v[l], 0);
        attn_tc_kernel<<<dim3(NQ / 128, NH, BS), 256>>>(qkb, vb, sab);
        gemm_ln<<<dim3(1, MROWS / 32), 256>>>(
            sab, sa_out_w + (size_t)l * D * D, sa_out_b + (size_t)l * D, prev,
            n2_w + (size_t)l * D, n2_b + (size_t)l * D, t1b, qpos, xbuf, MROWS, D);

        gemm_tc<32, 128, false><<<dim3(1, MROWS / 32), 256>>>(
            xbuf, owb + (size_t)l * 128 * D, obb + (size_t)l * 128, offawb, MROWS, 128, D);
        if (use_s) cudaStreamWaitEvent(0, g_aux.val_ev[l], 0);
        msda_kernel<<<(BS * NQ * NH + 7) / 8, 256>>>(
            valb + (size_t)l * VAL_STRIDE, offawb, ref, lsi, cab);
        gemm_ln<<<dim3(1, MROWS / 32), 256>>>(
            cab, ca_out_w + (size_t)l * D * D, ca_out_b + (size_t)l * D, t1b,
            n1_w + (size_t)l * D, n1_b + (size_t)l * D, t2b, nullptr, nullptr, MROWS, D);

        gemm_tc<128, 128, true><<<dim3(DFF / 128, MROWS / 128), 256>>>(
            t2b, ff1_w + (size_t)l * DFF * D, ff1_b + (size_t)l * DFF, ffnb, MROWS, DFF, D);
        gemm_ln<<<dim3(1, MROWS / 32), 256>>>(
            ffnb, ff2_w + (size_t)l * D * DFF, ff2_b + (size_t)l * D, t2b,
            n3_w + (size_t)l * D, n3_b + (size_t)l * D, cur, qpos, xbuf, MROWS, DFF);
        if (use_s && l + 1 < LNUM) cudaEventRecord(g_aux.ev_x[l + 1], 0);
    }

    const int hs_total = LNUM * MROWS * D;
    if (out_size > hs_total) {
        copy_refs_kernel<<<(LNUM * BS * NQ * 2 + 255) / 256, 256>>>(ref, out_hs + hs_total);
    }
}

// round 16
// speedup vs baseline: 1.3418x; 1.3418x over previous
#include <cuda_runtime.h>
#include <cuda_bf16.h>
#include <cstdint>

#define BS   4
#define NQ   1024
#define D    256
#define NH   8
#define NP   4
#define LNUM 6
#define DFF  1024
#define H_BEV 200
#define W_BEV 150
#define NV   (H_BEV * W_BEV)
#define DH   32
#define MROWS (BS * NQ)          // 4096

// ------------------------- scratch (static device globals) -------------------------
__device__ float g_xbuf[MROWS * D];
__device__ float g_qk[MROWS * 512];
__device__ float g_v[MROWS * D];
__device__ float g_sa[MROWS * D];
__device__ float g_t1[MROWS * D];
__device__ float g_t2[MROWS * D];
__device__ float g_val[(size_t)LNUM * BS * NV * D];
__device__ float g_ow[LNUM * 128 * D];
__device__ float g_ob[LNUM * 128];
__device__ float g_offaw[MROWS * 128];
__device__ float g_ca[MROWS * D];
__device__ float g_ffn[MROWS * DFF];
__device__ __nv_bfloat16 g_src_bf[(size_t)BS * NV * D];
__device__ __nv_bfloat16 g_valw_bf[LNUM * D * D];

// ------------------------- stream/event aux -------------------------
struct Aux {
    cudaStream_t sB = 0, sC = 0;
    cudaEvent_t fork = 0;
    cudaEvent_t val_ev[LNUM] = {};
    cudaEvent_t ev_x[LNUM] = {};
    cudaEvent_t ev_v[LNUM] = {};
    bool ok = false;
    Aux() {
        if (cudaStreamCreateWithFlags(&sB, cudaStreamNonBlocking) != cudaSuccess) return;
        if (cudaStreamCreateWithFlags(&sC, cudaStreamNonBlocking) != cudaSuccess) return;
        if (cudaEventCreateWithFlags(&fork, cudaEventDisableTiming) != cudaSuccess) return;
        for (int i = 0; i < LNUM; i++) {
            if (cudaEventCreateWithFlags(&val_ev[i], cudaEventDisableTiming) != cudaSuccess) return;
            if (cudaEventCreateWithFlags(&ev_x[i], cudaEventDisableTiming) != cudaSuccess) return;
            if (cudaEventCreateWithFlags(&ev_v[i], cudaEventDisableTiming) != cudaSuccess) return;
        }
        ok = true;
    }
};
static Aux g_aux;

// ------------------------- helpers -------------------------
__device__ __forceinline__ uint32_t f2tf(float f) {
    uint32_t r;
    asm("cvt.rna.tf32.f32 %0, %1;" : "=r"(r) : "f"(f));
    return r;
}
__device__ __forceinline__ void mma_tf32(float* c, const uint32_t* a, const uint32_t* b) {
    asm volatile("mma.sync.aligned.m16n8k8.row.col.f32.tf32.tf32.f32 "
                 "{%0,%1,%2,%3},{%4,%5,%6,%7},{%8,%9},{%0,%1,%2,%3};"
                 : "+f"(c[0]), "+f"(c[1]), "+f"(c[2]), "+f"(c[3])
                 : "r"(a[0]), "r"(a[1]), "r"(a[2]), "r"(a[3]), "r"(b[0]), "r"(b[1]));
}
__device__ __forceinline__ void mma_bf16(float* c, const uint32_t* a, const uint32_t* b) {
    asm volatile("mma.sync.aligned.m16n8k16.row.col.f32.bf16.bf16.f32 "
                 "{%0,%1,%2,%3},{%4,%5,%6,%7},{%8,%9},{%0,%1,%2,%3};"
                 : "+f"(c[0]), "+f"(c[1]), "+f"(c[2]), "+f"(c[3])
                 : "r"(a[0]), "r"(a[1]), "r"(a[2]), "r"(a[3]), "r"(b[0]), "r"(b[1]));
}
__device__ __forceinline__ void cp16(uint32_t smem_addr, const void* gptr, int src_bytes) {
    asm volatile("cp.async.ca.shared.global [%0], [%1], 16, %2;\n"
                 :: "r"(smem_addr), "l"(gptr), "r"(src_bytes));
}
__device__ __forceinline__ void cp_commit() { asm volatile("cp.async.commit_group;\n"); }
template <int N>
__device__ __forceinline__ void cp_wait() { asm volatile("cp.async.wait_group %0;\n" :: "n"(N)); }

// ------------------------- elementwise add -------------------------
__global__ void add_kernel(const float* __restrict__ a, const float* __restrict__ b,
                           float* __restrict__ o, int n) {
    int i = blockIdx.x * blockDim.x + threadIdx.x;
    if (i < n) o[i] = a[i] + b[i];
}

// ------------------------- f32 -> bf16 convert -------------------------
__global__ void cvt_bf16_kernel(const float* __restrict__ in, __nv_bfloat16* __restrict__ out,
                                size_t n4) {
    size_t i = (size_t)blockIdx.x * blockDim.x + threadIdx.x;
    if (i < n4) {
        float4 v = *reinterpret_cast<const float4*>(in + i * 4);
        __nv_bfloat162 lo = __floats2bfloat162_rn(v.x, v.y);
        __nv_bfloat162 hi = __floats2bfloat162_rn(v.z, v.w);
        *reinterpret_cast<__nv_bfloat162*>(out + i * 4)     = lo;
        *reinterpret_cast<__nv_bfloat162*>(out + i * 4 + 2) = hi;
    }
}

// ------------------------- pack off+aw weights -------------------------
__global__ void pack_offaw(const float* __restrict__ offw, const float* __restrict__ offb,
                           const float* __restrict__ aww, const float* __restrict__ awb,
                           float* __restrict__ W, float* __restrict__ B) {
    int i = blockIdx.x * blockDim.x + threadIdx.x;
    const int total = LNUM * 128 * D;
    if (i < total) {
        int l = i / (128 * D);
        int r = (i / D) % 128;
        int c = i % D;
        float v = 0.f;
        if (r < 64)      v = offw[((size_t)l * 64 + r) * D + c];
        else if (r < 96) v = aww[((size_t)l * 32 + (r - 64)) * D + c];
        W[i] = v;
    }
    if (i < LNUM * 128) {
        int l = i / 128, r = i % 128;
        float v = 0.f;
        if (r < 64)      v = offb[l * 64 + r];
        else if (r < 96) v = awb[l * 32 + (r - 64)];
        B[i] = v;
    }
}

// ------------------------- tf32 tensor-core GEMM (R14 config) -------------------------
template <int BM, int BN, bool RELU>
__global__ __launch_bounds__(256)
void gemm_tc(const float* __restrict__ A, const float* __restrict__ W,
             const float* __restrict__ bias, float* __restrict__ C,
             int M, int N, int K) {
    constexpr int ST  = 3;
    constexpr int WMC = (BM >= 32) ? (BM / 32) : 1;
    constexpr int WNC = 8 / WMC;
    constexpr int WCOLS = BN / WNC;
    constexpr int NT  = WCOLS / 8;

    __shared__ uint32_t As[ST][BM * 16];
    __shared__ uint32_t Bs[ST][BN * 16];

    const int tid  = threadIdx.x;
    const int lane = tid & 31;
    const int wid  = tid >> 5;
    const int wm   = wid % WMC;
    const int wn   = wid / WMC;
    const int g    = lane >> 2;
    const int t    = lane & 3;
    const int m0   = blockIdx.y * BM;
    const int n0   = blockIdx.x * BN;

    auto load_stage = [&](int s, int kt) {
        const int k0 = kt * 16;
        uint32_t sa = (uint32_t)__cvta_generic_to_shared(&As[s][0]);
        uint32_t sb = (uint32_t)__cvta_generic_to_shared(&Bs[s][0]);
#pragma unroll
        for (int c = tid; c < (BM + BN) * 4; c += 256) {
            int row = c >> 2, cg = (c & 3) * 4;
            if (c < BM * 4) {
                int gm = m0 + row;
                cp16(sa + (row * 16 + cg) * 4, &A[(size_t)gm * K + k0 + cg], gm < M ? 16 : 0);
            } else {
                int r = row - BM;
                cp16(sb + (r * 16 + cg) * 4, &W[(size_t)(n0 + r) * K + k0 + cg], 16);
            }
        }
        cp_commit();
    };

    float acc[2][NT][4];
#pragma unroll
    for (int i = 0; i < 2; i++)
#pragma unroll
        for (int j = 0; j < NT; j++)
#pragma unroll
            for (int c = 0; c < 4; c++) acc[i][j][c] = 0.f;

    const int KT = K / 16;
    load_stage(0, 0);
    if (KT > 1) load_stage(1 % ST, 1);

    for (int kt = 0; kt < KT; kt++) {
        cp_wait<1>();
        __syncthreads();
        if (kt + 2 < KT) load_stage((kt + 2) % ST, kt + 2);
        const int s = kt % ST;

        uint32_t afA[2][4], afB[2][4];
#pragma unroll
        for (int mt = 0; mt < 2; mt++) {
            const int row = wm * 32 + mt * 16 + g;
            uint4 ar0 = *reinterpret_cast<const uint4*>(&As[s][row * 16 + t * 4]);
            uint4 ar1 = *reinterpret_cast<const uint4*>(&As[s][(row + 8) * 16 + t * 4]);
            afA[mt][0] = ar0.x; afA[mt][1] = ar1.x; afA[mt][2] = ar0.y; afA[mt][3] = ar1.y;
            afB[mt][0] = ar0.z; afB[mt][1] = ar1.z; afB[mt][2] = ar0.w; afB[mt][3] = ar1.w;
        }
#pragma unroll
        for (int nt = 0; nt < NT; nt++) {
            uint4 br = *reinterpret_cast<const uint4*>(&Bs[s][(wn * WCOLS + nt * 8 + g) * 16 + t * 4]);
            uint32_t bA[2] = {br.x, br.y};
            uint32_t bB[2] = {br.z, br.w};
#pragma unroll
            for (int mt = 0; mt < 2; mt++) {
                mma_tf32(acc[mt][nt], afA[mt], bA);
                mma_tf32(acc[mt][nt], afB[mt], bB);
            }
        }
    }

#pragma unroll
    for (int nt = 0; nt < NT; nt++) {
        const int cb = n0 + wn * WCOLS + nt * 8 + t * 2;
        const float bv0 = bias[cb], bv1 = bias[cb + 1];
#pragma unroll
        for (int mt = 0; mt < 2; mt++) {
            int r0 = m0 + wm * 32 + mt * 16 + g;
            float o0 = acc[mt][nt][0] + bv0, o1 = acc[mt][nt][1] + bv1;
            float o2 = acc[mt][nt][2] + bv0, o3 = acc[mt][nt][3] + bv1;
            if (RELU) {
                o0 = fmaxf(o0, 0.f); o1 = fmaxf(o1, 0.f);
                o2 = fmaxf(o2, 0.f); o3 = fmaxf(o3, 0.f);
            }
            if (r0 < M)
                *reinterpret_cast<float2*>(&C[(size_t)r0 * N + cb]) = make_float2(o0, o1);
            if (r0 + 8 < M)
                *reinterpret_cast<float2*>(&C[(size_t)(r0 + 8) * N + cb]) = make_float2(o2, o3);
        }
    }
}

// ------------------------- bf16 tensor-core GEMM (BK=32, same loop shape) -----------------
// C[M,N] = A_bf[M,K] @ W_bf[N,K]^T + bias.  Virtual-k pairing; smem identical to tf32 BK=16.
__global__ __launch_bounds__(256)
void gemm_bf(const __nv_bfloat16* __restrict__ A, const __nv_bfloat16* __restrict__ W,
             const float* __restrict__ bias, float* __restrict__ C,
             int M, int N, int K) {
    constexpr int ST = 3, BM = 128, BN = 128, NT = 8, WCOLS = 64;
    __shared__ uint32_t As[ST][BM * 16];
    __shared__ uint32_t Bs[ST][BN * 16];

    const int tid  = threadIdx.x;
    const int lane = tid & 31;
    const int wid  = tid >> 5;
    const int wm   = wid & 3;
    const int wn   = wid >> 2;
    const int g    = lane >> 2;
    const int t    = lane & 3;
    const int m0   = blockIdx.y * BM;
    const int n0   = blockIdx.x * BN;

    auto load_stage = [&](int s, int kt) {
        const int k0 = kt * 32;                 // 32 bf16 per stage row
        uint32_t sa = (uint32_t)__cvta_generic_to_shared(&As[s][0]);
        uint32_t sb = (uint32_t)__cvta_generic_to_shared(&Bs[s][0]);
#pragma unroll
        for (int c = tid; c < (BM + BN) * 4; c += 256) {
            int row = c >> 2, cg = (c & 3) * 4;          // cg in words; *2 = bf16 elems
            if (c < BM * 4) {
                int gm = m0 + row;
                cp16(sa + (row * 16 + cg) * 4, &A[(size_t)gm * K + k0 + cg * 2], gm < M ? 16 : 0);
            } else {
                int r = row - BM;
                cp16(sb + (r * 16 + cg) * 4, &W[(size_t)(n0 + r) * K + k0 + cg * 2], 16);
            }
        }
        cp_commit();
    };

    float acc[2][NT][4];
#pragma unroll
    for (int i = 0; i < 2; i++)
#pragma unroll
        for (int j = 0; j < NT; j++)
#pragma unroll
            for (int c = 0; c < 4; c++) acc[i][j][c] = 0.f;

    const int KT = K / 32;
    load_stage(0, 0);
    if (KT > 1) load_stage(1 % ST, 1);

    for (int kt = 0; kt < KT; kt++) {
        cp_wait<1>();
        __syncthreads();
        if (kt + 2 < KT) load_stage((kt + 2) % ST, kt + 2);
        const int s = kt % ST;

        uint32_t afA[2][4], afB[2][4];
#pragma unroll
        for (int mt = 0; mt < 2; mt++) {
            const int row = wm * 32 + mt * 16 + g;
            uint4 ar0 = *reinterpret_cast<const uint4*>(&As[s][row * 16 + t * 4]);
            uint4 ar1 = *reinterpret_cast<const uint4*>(&As[s][(row + 8) * 16 + t * 4]);
            afA[mt][0] = ar0.x; afA[mt][1] = ar1.x; afA[mt][2] = ar0.y; afA[mt][3] = ar1.y;
            afB[mt][0] = ar0.z; afB[mt][1] = ar1.z; afB[mt][2] = ar0.w; afB[mt][3] = ar1.w;
        }
#pragma unroll
        for (int nt = 0; nt < NT; nt++) {
            uint4 br = *reinterpret_cast<const uint4*>(&Bs[s][(wn * WCOLS + nt * 8 + g) * 16 + t * 4]);
            uint32_t bA[2] = {br.x, br.y};
            uint32_t bB[2] = {br.z, br.w};
#pragma unroll
            for (int mt = 0; mt < 2; mt++) {
                mma_bf16(acc[mt][nt], afA[mt], bA);   // k16: physical k {8t..8t+3} x 2 rows-halves
                mma_bf16(acc[mt][nt], afB[mt], bB);   // k16: physical k {8t+4..8t+7}
            }
        }
    }

#pragma unroll
    for (int nt = 0; nt < NT; nt++) {
        const int cb = n0 + wn * WCOLS + nt * 8 + t * 2;
        const float bv0 = bias[cb], bv1 = bias[cb + 1];
#pragma unroll
        for (int mt = 0; mt < 2; mt++) {
            int r0 = m0 + wm * 32 + mt * 16 + g;
            float o0 = acc[mt][nt][0] + bv0, o1 = acc[mt][nt][1] + bv1;
            float o2 = acc[mt][nt][2] + bv0, o3 = acc[mt][nt][3] + bv1;
            if (r0 < M)
                *reinterpret_cast<float2*>(&C[(size_t)r0 * N + cb]) = make_float2(o0, o1);
            if (r0 + 8 < M)
                *reinterpret_cast<float2*>(&C[(size_t)(r0 + 8) * N + cb]) = make_float2(o2, o3);
        }
    }
}

// ------------------------- fused GEMM + bias + residual + LayerNorm -------------------------
__global__ __launch_bounds__(256)
void gemm_ln(const float* __restrict__ A, const float* __restrict__ W,
             const float* __restrict__ bias, const float* __restrict__ resid,
             const float* __restrict__ lnw, const float* __restrict__ lnb,
             float* __restrict__ C, const float* __restrict__ qpos,
             float* __restrict__ C2, int M, int K) {
    constexpr int ST = 3, BM = 32, BN = 256, NT = 4, WCOLS = 32;
    __shared__ uint32_t As[ST][BM * 16];
    __shared__ uint32_t Bs[ST][BN * 16];
    __shared__ float s_sum[BM][8];
    __shared__ float s_sq[BM][8];

    const int tid  = threadIdx.x;
    const int lane = tid & 31;
    const int wn   = tid >> 5;
    const int g    = lane >> 2;
    const int t    = lane & 3;
    const int m0   = blockIdx.y * BM;

    auto load_stage = [&](int s, int kt) {
        const int k0 = kt * 16;
        uint32_t sa = (uint32_t)__cvta_generic_to_shared(&As[s][0]);
        uint32_t sb = (uint32_t)__cvta_generic_to_shared(&Bs[s][0]);
#pragma unroll
        for (int c = tid; c < (BM + BN) * 4; c += 256) {
            int row = c >> 2, cg = (c & 3) * 4;
            if (c < BM * 4) {
                cp16(sa + (row * 16 + cg) * 4, &A[(size_t)(m0 + row) * K + k0 + cg], 16);
            } else {
                int r = row - BM;
                cp16(sb + (r * 16 + cg) * 4, &W[(size_t)r * K + k0 + cg], 16);
            }
        }
        cp_commit();
    };

    float acc[2][NT][4];
#pragma unroll
    for (int i = 0; i < 2; i++)
#pragma unroll
        for (int j = 0; j < NT; j++)
#pragma unroll
            for (int c = 0; c < 4; c++) acc[i][j][c] = 0.f;

    const int KT = K / 16;
    load_stage(0, 0);
    if (KT > 1) load_stage(1 % ST, 1);

    for (int kt = 0; kt < KT; kt++) {
        cp_wait<1>();
        __syncthreads();
        if (kt + 2 < KT) load_stage((kt + 2) % ST, kt + 2);
        const int s = kt % ST;

        uint32_t afA[2][4], afB[2][4];
#pragma unroll
        for (int mt = 0; mt < 2; mt++) {
            const int row = mt * 16 + g;
            uint4 ar0 = *reinterpret_cast<const uint4*>(&As[s][row * 16 + t * 4]);
            uint4 ar1 = *reinterpret_cast<const uint4*>(&As[s][(row + 8) * 16 + t * 4]);
            afA[mt][0] = ar0.x; afA[mt][1] = ar1.x; afA[mt][2] = ar0.y; afA[mt][3] = ar1.y;
            afB[mt][0] = ar0.z; afB[mt][1] = ar1.z; afB[mt][2] = ar0.w; afB[mt][3] = ar1.w;
        }
#pragma unroll
        for (int nt = 0; nt < NT; nt++) {
            uint4 br = *reinterpret_cast<const uint4*>(&Bs[s][(wn * WCOLS + nt * 8 + g) * 16 + t * 4]);
            uint32_t bA[2] = {br.x, br.y};
            uint32_t bB[2] = {br.z, br.w};
#pragma unroll
            for (int mt = 0; mt < 2; mt++) {
                mma_tf32(acc[mt][nt], afA[mt], bA);
                mma_tf32(acc[mt][nt], afB[mt], bB);
            }
        }
    }

    float vals[2][NT][4];
    float rsum[4] = {0.f, 0.f, 0.f, 0.f};
    float rsq[4]  = {0.f, 0.f, 0.f, 0.f};
#pragma unroll
    for (int mt = 0; mt < 2; mt++) {
        const int r0 = m0 + mt * 16 + g, r1 = r0 + 8;
#pragma unroll
        for (int nt = 0; nt < NT; nt++) {
            const int cb = wn * WCOLS + nt * 8 + t * 2;
            const float b0 = bias[cb], b1 = bias[cb + 1];
            float2 rr0 = *reinterpret_cast<const float2*>(&resid[(size_t)r0 * 256 + cb]);
            float2 rr1 = *reinterpret_cast<const float2*>(&resid[(size_t)r1 * 256 + cb]);
            float v0 = acc[mt][nt][0] + b0 + rr0.x;
            float v1 = acc[mt][nt][1] + b1 + rr0.y;
            float v2 = acc[mt][nt][2] + b0 + rr1.x;
            float v3 = acc[mt][nt][3] + b1 + rr1.y;
            vals[mt][nt][0] = v0; vals[mt][nt][1] = v1;
            vals[mt][nt][2] = v2; vals[mt][nt][3] = v3;
            rsum[mt * 2]     += v0 + v1;  rsq[mt * 2]     += v0 * v0 + v1 * v1;
            rsum[mt * 2 + 1] += v2 + v3;  rsq[mt * 2 + 1] += v2 * v2 + v3 * v3;
        }
    }
    const unsigned F = 0xffffffffu;
#pragma unroll
    for (int sl = 0; sl < 4; sl++) {
        rsum[sl] += __shfl_xor_sync(F, rsum[sl], 1);
        rsum[sl] += __shfl_xor_sync(F, rsum[sl], 2);
        rsq[sl]  += __shfl_xor_sync(F, rsq[sl], 1);
        rsq[sl]  += __shfl_xor_sync(F, rsq[sl], 2);
    }
    if (t == 0) {
#pragma unroll
        for (int sl = 0; sl < 4; sl++) {
            int rowl = (sl >> 1) * 16 + g + (sl & 1) * 8;
            s_sum[rowl][wn] = rsum[sl];
            s_sq[rowl][wn]  = rsq[sl];
        }
    }
    __syncthreads();

    float mean_[4], rstd_[4];
#pragma unroll
    for (int sl = 0; sl < 4; sl++) {
        int rowl = (sl >> 1) * 16 + g + (sl & 1) * 8;
        float sv = 0.f, q = 0.f;
#pragma unroll
        for (int w8 = 0; w8 < 8; w8++) { sv += s_sum[rowl][w8]; q += s_sq[rowl][w8]; }
        float mean = sv * (1.f / 256.f);
        float var  = q * (1.f / 256.f) - mean * mean;
        mean_[sl] = mean;
        rstd_[sl] = rsqrtf(var + 1e-5f);
    }

#pragma unroll
    for (int mt = 0; mt < 2; mt++) {
        const int r0 = m0 + mt * 16 + g, r1 = r0 + 8;
        const float mA = mean_[mt * 2],     rA = rstd_[mt * 2];
        const float mB = mean_[mt * 2 + 1], rB = rstd_[mt * 2 + 1];
#pragma unroll
        for (int nt = 0; nt < NT; nt++) {
            const int cb = wn * WCOLS + nt * 8 + t * 2;
            const float w0 = lnw[cb], w1 = lnw[cb + 1];
            const float lb0 = lnb[cb], lb1 = lnb[cb + 1];
            float o0 = (vals[mt][nt][0] - mA) * rA * w0 + lb0;
            float o1 = (vals[mt][nt][1] - mA) * rA * w1 + lb1;
            float o2 = (vals[mt][nt][2] - mB) * rB * w0 + lb0;
            float o3 = (vals[mt][nt][3] - mB) * rB * w1 + lb1;
            *reinterpret_cast<float2*>(&C[(size_t)r0 * 256 + cb]) = make_float2(o0, o1);
            *reinterpret_cast<float2*>(&C[(size_t)r1 * 256 + cb]) = make_float2(o2, o3);
            if (C2) {
                float2 q0 = *reinterpret_cast<const float2*>(&qpos[(size_t)r0 * 256 + cb]);
                float2 q1 = *reinterpret_cast<const float2*>(&qpos[(size_t)r1 * 256 + cb]);
                *reinterpret_cast<float2*>(&C2[(size_t)r0 * 256 + cb]) =
                    make_float2(o0 + q0.x, o1 + q0.y);
                *reinterpret_cast<float2*>(&C2[(size_t)r1 * 256 + cb]) =
                    make_float2(o2 + q1.x, o3 + q1.y);
            }
        }
    }
}

// ------------------------- tensor-core flash attention (cp.async double-buffered) ----------
#define LKP 36
#define LVP 40
__global__ __launch_bounds__(256)
void attn_tc_kernel(const float* __restrict__ QK, const float* __restrict__ V,
                    float* __restrict__ O) {
    __shared__ uint32_t Ks[2][64 * LKP];
    __shared__ uint32_t Vs[2][64 * LVP];

    const int q0   = blockIdx.x * 128;
    const int h    = blockIdx.y;
    const int b    = blockIdx.z;
    const int tid  = threadIdx.x;
    const int lane = tid & 31;
    const int w    = tid >> 5;
    const int g    = lane >> 2;
    const int t    = lane & 3;

    auto load_tile = [&](int bufi, int t0) {
        uint32_t kb = (uint32_t)__cvta_generic_to_shared(&Ks[bufi][0]);
        uint32_t vbs = (uint32_t)__cvta_generic_to_shared(&Vs[bufi][0]);
#pragma unroll
        for (int j = 0; j < 2; j++) {
            int c = tid + j * 256;
            int row = c >> 3, cg = (c & 7) * 4;
            cp16(kb + (row * LKP + cg) * 4,
                 &QK[(size_t)(b * NQ + t0 + row) * 512 + 256 + h * 32 + cg], 16);
        }
#pragma unroll
        for (int j = 0; j < 2; j++) {
            int c = tid + j * 256;
            int row = c >> 3, cg = (c & 7) * 4;
            cp16(vbs + (row * LVP + cg) * 4,
                 &V[(size_t)(b * NQ + t0 + row) * 256 + h * 32 + cg], 16);
        }
        cp_commit();
    };

    uint32_t af[4][4];
    {
        const int r0 = b * NQ + q0 + w * 16 + g;
        const int r1 = r0 + 8;
        const float scq = 0.17677669529663687f;
        const float* Q0 = &QK[(size_t)r0 * 512 + h * 32];
        const float* Q1 = &QK[(size_t)r1 * 512 + h * 32];
#pragma unroll
        for (int ks = 0; ks < 4; ks++) {
            af[ks][0] = f2tf(Q0[ks * 8 + t] * scq);
            af[ks][1] = f2tf(Q1[ks * 8 + t] * scq);
            af[ks][2] = f2tf(Q0[ks * 8 + t + 4] * scq);
            af[ks][3] = f2tf(Q1[ks * 8 + t + 4] * scq);
        }
    }

    float oc[4][4];
#pragma unroll
    for (int i = 0; i < 4; i++)
#pragma unroll
        for (int j = 0; j < 4; j++) oc[i][j] = 0.f;
    float m0r = -1e30f, m1r = -1e30f, l0 = 0.f, l1 = 0.f;
    const unsigned F = 0xffffffffu;

    load_tile(0, 0);
    int buf = 0;
    const int NTILES = NQ / 64;

    for (int it = 0; it < NTILES; it++) {
        if (it + 1 < NTILES) {
            load_tile(buf ^ 1, (it + 1) * 64);
            cp_wait<1>();
        } else {
            cp_wait<0>();
        }
        __syncthreads();

        float sc[8][4];
#pragma unroll
        for (int nt = 0; nt < 8; nt++) {
            sc[nt][0] = sc[nt][1] = sc[nt][2] = sc[nt][3] = 0.f;
            uint32_t bf[4][2];
#pragma unroll
            for (int ks = 0; ks < 4; ks++) {
                const uint32_t* base = &Ks[buf][(nt * 8 + g) * LKP + ks * 8];
                bf[ks][0] = base[t];
                bf[ks][1] = base[t + 4];
            }
#pragma unroll
            for (int ks = 0; ks < 4; ks++) mma_tf32(sc[nt], af[ks], bf[ks]);
        }

        float mt0 = -1e30f, mt1 = -1e30f;
#pragma unroll
        for (int nt = 0; nt < 8; nt++) {
            mt0 = fmaxf(mt0, fmaxf(sc[nt][0], sc[nt][1]));
            mt1 = fmaxf(mt1, fmaxf(sc[nt][2], sc[nt][3]));
        }
        mt0 = fmaxf(mt0, __shfl_xor_sync(F, mt0, 1));
        mt0 = fmaxf(mt0, __shfl_xor_sync(F, mt0, 2));
        mt1 = fmaxf(mt1, __shfl_xor_sync(F, mt1, 1));
        mt1 = fmaxf(mt1, __shfl_xor_sync(F, mt1, 2));
        const float mn0 = fmaxf(m0r, mt0), mn1 = fmaxf(m1r, mt1);
        const float sc0 = __expf(m0r - mn0), sc1 = __expf(m1r - mn1);

        uint32_t pf[8][4];
        float s0 = 0.f, s1 = 0.f;
#pragma unroll
        for (int nt = 0; nt < 8; nt++) {
            float p0 = __expf(sc[nt][0] - mn0);
            float p1 = __expf(sc[nt][1] - mn0);
            float p2 = __expf(sc[nt][2] - mn1);
            float p3 = __expf(sc[nt][3] - mn1);
            s0 += p0 + p1; s1 += p2 + p3;
            pf[nt][0] = f2tf(p0); pf[nt][1] = f2tf(p1);
            pf[nt][2] = f2tf(p2); pf[nt][3] = f2tf(p3);
        }
        s0 += __shfl_xor_sync(F, s0, 1); s0 += __shfl_xor_sync(F, s0, 2);
        s1 += __shfl_xor_sync(F, s1, 1); s1 += __shfl_xor_sync(F, s1, 2);
        l0 = l0 * sc0 + s0;
        l1 = l1 * sc1 + s1;
        m0r = mn0; m1r = mn1;
#pragma unroll
        for (int nt = 0; nt < 4; nt++) {
            oc[nt][0] *= sc0; oc[nt][1] *= sc0;
            oc[nt][2] *= sc1; oc[nt][3] *= sc1;
        }

        const int src0 = (lane & ~3) | (t >> 1);
        const int src1 = src0 + 2;
        const bool odd = (t & 1);
#pragma unroll
        for (int kt = 0; kt < 8; kt++) {
            uint32_t a[4];
            uint32_t x0 = __shfl_sync(F, pf[kt][0], src0);
            uint32_t x1 = __shfl_sync(F, pf[kt][1], src0);
            a[0] = odd ? x1 : x0;
            uint32_t x2 = __shfl_sync(F, pf[kt][2], src0);
            uint32_t x3 = __shfl_sync(F, pf[kt][3], src0);
            a[1] = odd ? x3 : x2;
            x0 = __shfl_sync(F, pf[kt][0], src1);
            x1 = __shfl_sync(F, pf[kt][1], src1);
            a[2] = odd ? x1 : x0;
            x2 = __shfl_sync(F, pf[kt][2], src1);
            x3 = __shfl_sync(F, pf[kt][3], src1);
            a[3] = odd ? x3 : x2;
#pragma unroll
            for (int nt = 0; nt < 4; nt++) {
                uint32_t bfv[2];
                bfv[0] = Vs[buf][(kt * 8 + t) * LVP + nt * 8 + g];
                bfv[1] = Vs[buf][(kt * 8 + t + 4) * LVP + nt * 8 + g];
                mma_tf32(oc[nt], a, bfv);
            }
        }
        __syncthreads();
        buf ^= 1;
    }

    const float inv0 = 1.f / l0, inv1 = 1.f / l1;
    const int r0 = b * NQ + q0 + w * 16 + g;
#pragma unroll
    for (int nt = 0; nt < 4; nt++) {
        const int col = h * 32 + nt * 8 + t * 2;
        *reinterpret_cast<float2*>(&O[(size_t)r0 * 256 + col]) =
            make_float2(oc[nt][0] * inv0, oc[nt][1] * inv0);
        *reinterpret_cast<float2*>(&O[(size_t)(r0 + 8) * 256 + col]) =
            make_float2(oc[nt][2] * inv1, oc[nt][3] * inv1);
    }
}

// ------------------------- MSDA sampling -------------------------
__global__ void msda_kernel(const float* __restrict__ val, const float* __restrict__ offaw,
                            const float* __restrict__ ref, const int* __restrict__ lsi,
                            float* __restrict__ out) {
    const int warp = (blockIdx.x * blockDim.x + threadIdx.x) >> 5;
    const int lane = threadIdx.x & 31;
    if (warp >= BS * NQ * NH) return;
    const int h  = warp % NH;
    const int bq = warp / NH;
    const int b  = bq / NQ;
    const int base = lsi[0];

    const float rx = ref[bq * 2 + 0] * (float)W_BEV - 0.5f;
    const float ry = ref[bq * 2 + 1] * (float)H_BEV - 0.5f;

    const float* row = &offaw[(size_t)bq * 128];
    float a0 = row[64 + h * NP + 0];
    float a1 = row[64 + h * NP + 1];
    float a2 = row[64 + h * NP + 2];
    float a3 = row[64 + h * NP + 3];
    float mx = fmaxf(fmaxf(a0, a1), fmaxf(a2, a3));
    float e0 = __expf(a0 - mx), e1 = __expf(a1 - mx), e2 = __expf(a2 - mx), e3 = __expf(a3 - mx);
    float inv = 1.f / (e0 + e1 + e2 + e3);
    float ap[4] = {e0 * inv, e1 * inv, e2 * inv, e3 * inv};

    float accv = 0.f;
#pragma unroll
    for (int p = 0; p < NP; p++) {
        float ox = row[(h * NP + p) * 2 + 0];
        float oy = row[(h * NP + p) * 2 + 1];
        float x = rx + ox, y = ry + oy;
        float x0f = floorf(x), y0f = floorf(y);
        int x0 = (int)x0f, y0 = (int)y0f;
        float fx = x - x0f, fy = y - y0f;
        float wgt[4] = {(1.f - fx) * (1.f - fy), fx * (1.f - fy), (1.f - fx) * fy, fx * fy};
        int xs[4] = {x0, x0 + 1, x0, x0 + 1};
        int ys[4] = {y0, y0, y0 + 1, y0 + 1};
#pragma unroll
        for (int c = 0; c < 4; c++) {
            int xi = xs[c], yi = ys[c];
            if (xi >= 0 && xi < W_BEV && yi >= 0 && yi < H_BEV) {
                float vv = val[((size_t)(b * NV + base + yi * W_BEV + xi)) * D + h * DH + lane];
                accv += ap[p] * wgt[c] * vv;
            }
        }
    }
    out[(size_t)bq * D + h * DH + lane] = accv;
}

// ------------------------- refs tail -------------------------
__global__ void copy_refs_kernel(const float* __restrict__ ref, float* __restrict__ out) {
    int i = blockIdx.x * blockDim.x + threadIdx.x;
    const int n1 = BS * NQ * 2;
    if (i < LNUM * n1) out[i] = ref[i % n1];
}

// ------------------------- launch -------------------------
extern "C" void kernel_launch(void* const* d_in, const int* in_sizes, int n_in,
                              void* d_out, int out_size) {
    const float* query    = (const float*)d_in[0];
    const float* qpos     = (const float*)d_in[1];
    const float* ref      = (const float*)d_in[2];
    const float* src      = (const float*)d_in[3];
    const int*   lsi      = (const int*)d_in[5];
    const float* sa_in_w  = (const float*)d_in[6];
    const float* sa_in_b  = (const float*)d_in[7];
    const float* sa_out_w = (const float*)d_in[8];
    const float* sa_out_b = (const float*)d_in[9];
    const float* ca_off_w = (const float*)d_in[10];
    const float* ca_off_b = (const float*)d_in[11];
    const float* ca_aw_w  = (const float*)d_in[12];
    const float* ca_aw_b  = (const float*)d_in[13];
    const float* ca_val_w = (const float*)d_in[14];
    const float* ca_val_b = (const float*)d_in[15];
    const float* ca_out_w = (const float*)d_in[16];
    const float* ca_out_b = (const float*)d_in[17];
    const float* n1_w     = (const float*)d_in[18];
    const float* n1_b     = (const float*)d_in[19];
    const float* n2_w     = (const float*)d_in[20];
    const float* n2_b     = (const float*)d_in[21];
    const float* n3_w     = (const float*)d_in[22];
    const float* n3_b     = (const float*)d_in[23];
    const float* ff1_w    = (const float*)d_in[24];
    const float* ff1_b    = (const float*)d_in[25];
    const float* ff2_w    = (const float*)d_in[26];
    const float* ff2_b    = (const float*)d_in[27];

    float *xbuf, *qkb, *vb, *sab, *t1b, *t2b, *valb, *owb, *obb, *offawb, *cab, *ffnb;
    __nv_bfloat16 *srcbf, *valwbf;
    cudaGetSymbolAddress((void**)&xbuf, g_xbuf);
    cudaGetSymbolAddress((void**)&qkb,  g_qk);
    cudaGetSymbolAddress((void**)&vb,   g_v);
    cudaGetSymbolAddress((void**)&sab,  g_sa);
    cudaGetSymbolAddress((void**)&t1b,  g_t1);
    cudaGetSymbolAddress((void**)&t2b,  g_t2);
    cudaGetSymbolAddress((void**)&valb, g_val);
    cudaGetSymbolAddress((void**)&owb,  g_ow);
    cudaGetSymbolAddress((void**)&obb,  g_ob);
    cudaGetSymbolAddress((void**)&offawb, g_offaw);
    cudaGetSymbolAddress((void**)&cab,  g_ca);
    cudaGetSymbolAddress((void**)&ffnb, g_ffn);
    cudaGetSymbolAddress((void**)&srcbf,  g_src_bf);
    cudaGetSymbolAddress((void**)&valwbf, g_valw_bf);

    float* out_hs = (float*)d_out;
    const int NTOK = MROWS * D;
    const size_t VAL_STRIDE = (size_t)BS * NV * D;

    const bool use_s = g_aux.ok;
    cudaStream_t sB = use_s ? g_aux.sB : 0;
    cudaStream_t sC = use_s ? g_aux.sC : 0;

    pack_offaw<<<(LNUM * 128 * D + 255) / 256, 256>>>(ca_off_w, ca_off_b, ca_aw_w, ca_aw_b,
                                                      owb, obb);

    if (use_s) {
        cudaEventRecord(g_aux.fork, 0);
        cudaStreamWaitEvent(sB, g_aux.fork, 0);
        cudaStreamWaitEvent(sC, g_aux.fork, 0);
    }

    // ---- sB: convert src + val weights to bf16, then 6 bf16 value projections ----
    {
        size_t n4 = VAL_STRIDE / 4;
        cvt_bf16_kernel<<<(unsigned)((n4 + 255) / 256), 256, 0, sB>>>(src, srcbf, n4);
        size_t w4 = (size_t)LNUM * D * D / 4;
        cvt_bf16_kernel<<<(unsigned)((w4 + 255) / 256), 256, 0, sB>>>(ca_val_w, valwbf, w4);
    }
    for (int l = 0; l < LNUM; l++) {
        gemm_bf<<<dim3(D / 128, (BS * NV + 127) / 128), 256, 0, sB>>>(
            srcbf, valwbf + (size_t)l * D * D, ca_val_b + (size_t)l * D,
            valb + (size_t)l * VAL_STRIDE, BS * NV, D, D);
        if (use_s) cudaEventRecord(g_aux.val_ev[l], sB);
    }

    add_kernel<<<(NTOK + 255) / 256, 256>>>(query, qpos, xbuf, NTOK);
    if (use_s) cudaEventRecord(g_aux.ev_x[0], 0);

    for (int l = 0; l < LNUM; l++) {
        const float* prev = (l == 0) ? query : out_hs + (size_t)(l - 1) * NTOK;
        float* cur = out_hs + (size_t)l * NTOK;

        if (use_s) {
            cudaStreamWaitEvent(sC, g_aux.ev_x[l], 0);
            gemm_tc<64, 128, false><<<dim3(D / 128, MROWS / 64), 256, 0, sC>>>(
                prev, sa_in_w + (size_t)l * 3 * D * D + (size_t)2 * D * D,
                sa_in_b + (size_t)l * 3 * D + 2 * D, vb, MROWS, D, D);
            cudaEventRecord(g_aux.ev_v[l], sC);
        } else {
            gemm_tc<64, 128, false><<<dim3(D / 128, MROWS / 64), 256>>>(
                prev, sa_in_w + (size_t)l * 3 * D * D + (size_t)2 * D * D,
                sa_in_b + (size_t)l * 3 * D + 2 * D, vb, MROWS, D, D);
        }

        gemm_tc<64, 128, false><<<dim3(512 / 128, MROWS / 64), 256>>>(
            xbuf, sa_in_w + (size_t)l * 3 * D * D, sa_in_b + (size_t)l * 3 * D,
            qkb, MROWS, 512, D);
        if (use_s) cudaStreamWaitEvent(0, g_aux.ev_v[l], 0);
        attn_tc_kernel<<<dim3(NQ / 128, NH, BS), 256>>>(qkb, vb, sab);
        gemm_ln<<<dim3(1, MROWS / 32), 256>>>(
            sab, sa_out_w + (size_t)l * D * D, sa_out_b + (size_t)l * D, prev,
            n2_w + (size_t)l * D, n2_b + (size_t)l * D, t1b, qpos, xbuf, MROWS, D);

        gemm_tc<32, 128, false><<<dim3(1, MROWS / 32), 256>>>(
            xbuf, owb + (size_t)l * 128 * D, obb + (size_t)l * 128, offawb, MROWS, 128, D);
        if (use_s) cudaStreamWaitEvent(0, g_aux.val_ev[l], 0);
        msda_kernel<<<(BS * NQ * NH + 7) / 8, 256>>>(
            valb + (size_t)l * VAL_STRIDE, offawb, ref, lsi, cab);
        gemm_ln<<<dim3(1, MROWS / 32), 256>>>(
            cab, ca_out_w + (size_t)l * D * D, ca_out_b + (size_t)l * D, t1b,
            n1_w + (size_t)l * D, n1_b + (size_t)l * D, t2b, nullptr, nullptr, MROWS, D);

        gemm_tc<128, 128, true><<<dim3(DFF / 128, MROWS / 128), 256>>>(
            t2b, ff1_w + (size_t)l * DFF * D, ff1_b + (size_t)l * DFF, ffnb, MROWS, DFF, D);
        gemm_ln<<<dim3(1, MROWS / 32), 256>>>(
            ffnb, ff2_w + (size_t)l * D * DFF, ff2_b + (size_t)l * D, t2b,
            n3_w + (size_t)l * D, n3_b + (size_t)l * D, cur, qpos, xbuf, MROWS, DFF);
        if (use_s && l + 1 < LNUM) cudaEventRecord(g_aux.ev_x[l + 1], 0);
    }

    const int hs_total = LNUM * MROWS * D;
    if (out_size > hs_total) {
        copy_refs_kernel<<<(LNUM * BS * NQ * 2 + 255) / 256, 256>>>(ref, out_hs + hs_total);
    }
}